// round 3
// baseline (speedup 1.0000x reference)
#include <cuda_runtime.h>
#include <cstdint>
#include <cstddef>

// ============================================================================
// Compile-time basis construction (double precision, folded to fp32 literals)
// ============================================================================
__host__ __device__ constexpr double cexp_(double v) {
    double t = 1.0, s = 1.0;
    for (int n = 1; n < 90; ++n) { t *= v / n; s += t; }
    return s;
}
__host__ __device__ constexpr double csqrt_(double v) {
    if (v <= 0.0) return 0.0;
    double x = v < 1.0 ? 1.0 : v;
    for (int i = 0; i < 80; ++i) x = 0.5 * (x + v / x);
    return x;
}

struct Basis {
    float b0[3][5][5];      // ring bases (k=0), r0 = 0,1,2
    float br[3][2][5][5];   // ring(r0)*cos(k*theta), k=1..3, r0 = 1,2
    float bi[3][2][5][5];   // ring(r0)*sin(k*theta)
};

__host__ __device__ constexpr Basis make_basis() {
    Basis B{};
    for (int yy = 0; yy < 5; ++yy) {
        for (int xx = 0; xx < 5; ++xx) {
            double ys = yy - 2.0, xs = xx - 2.0;
            double r = csqrt_(ys * ys + xs * xs);
            double cth = r > 0.0 ? xs / r : 1.0;   // cos(atan2(ys,xs))
            double sth = r > 0.0 ? ys / r : 0.0;   // sin(atan2(ys,xs))
            double ring0 = cexp_(-(r - 0.0) * (r - 0.0) / 0.72);
            double ring1 = cexp_(-(r - 1.0) * (r - 1.0) / 0.72);
            double ring2 = cexp_(-(r - 2.0) * (r - 2.0) / 0.72);
            B.b0[0][yy][xx] = (float)ring0;
            B.b0[1][yy][xx] = (float)ring1;
            B.b0[2][yy][xx] = (float)ring2;
            double ck = cth, sk = sth;              // cos(k*th), sin(k*th), k=1
            for (int k = 0; k < 3; ++k) {
                B.br[k][0][yy][xx] = (float)(ring1 * ck);
                B.br[k][1][yy][xx] = (float)(ring2 * ck);
                B.bi[k][0][yy][xx] = (float)(ring1 * sk);
                B.bi[k][1][yy][xx] = (float)(ring2 * sk);
                double cn = ck * cth - sk * sth;
                double sn = sk * cth + ck * sth;
                ck = cn; sk = sn;
            }
        }
    }
    return B;
}

// ============================================================================
// Intermediate: y[n][o*9+c][192*192]  (channel-mixed x at input resolution)
// ============================================================================
__device__ float g_y[(size_t)8 * 144 * 192 * 192];

// ============================================================================
// Pass 1: y[n, o*9+c, p] = sum_i weights[o,i,c] * x[n,i,p]
// Pure per-pixel GEMM: M = 8*36864 pixels, N = 144, K = 32.
// Block: 384 threads = 24 pixel-groups (8 px each) x 16 o.  Tile = 192 pixels.
// ============================================================================
__global__ __launch_bounds__(384) void pass1(const float* __restrict__ x,
                                             const float* __restrict__ wts) {
    __shared__ float xs[32 * 192];      // [i][p]
    __shared__ float ws[144 * 33];      // [o*9+c][i], padded stride 33
    const int n = blockIdx.y;
    const int p0 = blockIdx.x * 192;
    const int tid = threadIdx.x;

    // Load + transpose weights (o,i,c) -> [(o,c)][i]
    for (int e = tid; e < 4608; e += 384) {
        int o = e / 288, r = e % 288, i = r / 9, c = r % 9;
        ws[(o * 9 + c) * 33 + i] = wts[e];
    }
    // Load x tile (coalesced float4)
    const float* xb = x + (size_t)n * 32 * 36864 + p0;
    for (int e = tid; e < 1536; e += 384) {
        int i = e / 48, p4 = e % 48;
        *(float4*)(xs + i * 192 + p4 * 4) =
            *(const float4*)(xb + (size_t)i * 36864 + p4 * 4);
    }
    __syncthreads();

    const int o  = tid & 15;
    const int pg = tid >> 4;   // 0..23

    float acc[9][8];
#pragma unroll
    for (int c = 0; c < 9; ++c)
#pragma unroll
        for (int p = 0; p < 8; ++p) acc[c][p] = 0.f;

    const float* xg = xs + pg * 8;
    const float* wg = ws + o * 9 * 33;

#pragma unroll 4
    for (int i = 0; i < 32; ++i) {
        float4 xa = *(const float4*)(xg + i * 192);
        float4 xc = *(const float4*)(xg + i * 192 + 4);
        float xv[8] = {xa.x, xa.y, xa.z, xa.w, xc.x, xc.y, xc.z, xc.w};
#pragma unroll
        for (int c = 0; c < 9; ++c) {
            float wv = wg[c * 33 + i];
#pragma unroll
            for (int p = 0; p < 8; ++p) acc[c][p] += wv * xv[p];
        }
    }

    size_t base = ((size_t)n * 144 + o * 9) * 36864 + p0 + pg * 8;
#pragma unroll
    for (int c = 0; c < 9; ++c) {
        float* yo = g_y + base + (size_t)c * 36864;
        *(float4*)yo       = make_float4(acc[c][0], acc[c][1], acc[c][2], acc[c][3]);
        *(float4*)(yo + 4) = make_float4(acc[c][4], acc[c][5], acc[c][6], acc[c][7]);
    }
}

// ============================================================================
// Pass 2: steered transpose-conv combine + modulation + rho/bias epilogue.
//
// Output pixel p (per dim): taps v with v == p (mod 2), source i = (p+2-v)/2.
//   even p: i in {p/2-1, p/2, p/2+1} <-> v = 4,2,0
//   odd  p: i in {(p-1)/2, (p+1)/2}  <-> v = 3,1
// Thread handles a 2x2 output quad -> shared 3x3 input window per channel.
// ============================================================================
__device__ __forceinline__ float dotT(const float (&T)[5][5],
                                      const float (&w)[3][3],
                                      int SY, int SX) {
    float s = 0.f;
#pragma unroll
    for (int dy = 0; dy < 3; ++dy) {
        if (dy < SY) continue;
        int vy = (SY ? 5 : 4) - 2 * dy;
#pragma unroll
        for (int dx = 0; dx < 3; ++dx) {
            if (dx < SX) continue;
            int vx = (SX ? 5 : 4) - 2 * dx;
            float cf = T[vy][vx];
            if (cf != 0.f) s += cf * w[dy][dx];
        }
    }
    return s;
}

__global__ __launch_bounds__(512) void pass2(const float* __restrict__ alpha,
                                             const float* __restrict__ bias,
                                             float* __restrict__ out) {
    constexpr Basis BAS = make_basis();
    extern __shared__ float ysm[];   // [144][18][19]

    const int tx = blockIdx.x, ty = blockIdx.y, n = blockIdx.z;
    const int tid = threadIdx.x;
    const int ix0 = tx * 16, iy0 = ty * 16;

    // Stage y tile (with 1-halo, zero-padded at image edges) into smem
    const float* yg = g_y + (size_t)n * 144 * 36864;
    for (int e = tid; e < 144 * 324; e += 512) {
        int oc = e / 324;
        int rem = e - oc * 324;
        int r = rem / 18;
        int cc = rem - r * 18;
        int gy = iy0 - 1 + r, gx = ix0 - 1 + cc;
        float v = 0.f;
        if ((unsigned)gy < 192u && (unsigned)gx < 192u)
            v = yg[(size_t)oc * 36864 + gy * 192 + gx];
        ysm[(oc * 18 + r) * 19 + cc] = v;
    }
    __syncthreads();

    const int q  = tid & 255;  // quad id (16x16 quads = 32x32 px tile)
    const int oh = tid >> 8;   // o half: 0 -> o 0..7, 1 -> o 8..15
    const int qy = q >> 4, qx = q & 15;
    const int py0 = ty * 32 + 2 * qy;
    const int px0 = tx * 32 + 2 * qx;

    // Per-pixel modulation: rho, cos(k th), sin(k th)  (Chebyshev recursion)
    float RHO[2][2], CK[3][2][2], SK[3][2][2];
    {
        const float* a0p = alpha + (size_t)n * 147456 + (size_t)py0 * 384 + px0;
        const float* a1p = a0p + (size_t)8 * 147456;
#pragma unroll
        for (int sy = 0; sy < 2; ++sy)
#pragma unroll
            for (int sx = 0; sx < 2; ++sx) {
                float a0 = a0p[sy * 384 + sx];
                float a1 = a1p[sy * 384 + sx];
                float rho = sqrtf(a0 * a0 + a1 * a1);
                float inv = 1.0f / (rho + 1e-8f);
                float c1 = a0 * inv, s1 = a1 * inv;
                float c2 = c1 * c1 - s1 * s1;
                float s2 = s1 * c1 + c1 * s1;
                float c3 = c2 * c1 - s2 * s1;
                float s3 = s2 * c1 + c2 * s1;
                RHO[sy][sx] = rho;
                CK[0][sy][sx] = c1; SK[0][sy][sx] = s1;
                CK[1][sy][sx] = c2; SK[1][sy][sx] = s2;
                CK[2][sy][sx] = c3; SK[2][sy][sx] = s3;
            }
    }

    for (int o = oh * 8; o < oh * 8 + 8; ++o) {
        float acc[2][2] = {{0.f, 0.f}, {0.f, 0.f}};
#pragma unroll
        for (int c = 0; c < 9; ++c) {
            const float* wbp = ysm + ((o * 9 + c) * 18 + qy) * 19 + qx;
            float w[3][3];
#pragma unroll
            for (int dy = 0; dy < 3; ++dy)
#pragma unroll
                for (int dx = 0; dx < 3; ++dx) w[dy][dx] = wbp[dy * 19 + dx];

            if (c < 3) {
                acc[0][0] += dotT(BAS.b0[c], w, 0, 0);
                acc[0][1] += dotT(BAS.b0[c], w, 0, 1);
                acc[1][0] += dotT(BAS.b0[c], w, 1, 0);
                acc[1][1] += dotT(BAS.b0[c], w, 1, 1);
            } else {
                const int k = (c - 3) >> 1;   // harmonic index 0..2 (k+1)
                const int j = (c - 3) & 1;    // radial index
#pragma unroll
                for (int sy = 0; sy < 2; ++sy)
#pragma unroll
                    for (int sx = 0; sx < 2; ++sx) {
                        float dR = dotT(BAS.br[k][j], w, sy, sx);
                        float dI = dotT(BAS.bi[k][j], w, sy, sx);
                        acc[sy][sx] += dR * CK[k][sy][sx] + dI * SK[k][sy][sx];
                    }
            }
        }
        float bo = bias[o];
#pragma unroll
        for (int sy = 0; sy < 2; ++sy) {
            float2 v;
            v.x = RHO[sy][0] * acc[sy][0] + bo;
            v.y = RHO[sy][1] * acc[sy][1] + bo;
            *(float2*)(out + ((size_t)(n * 16 + o)) * 147456 +
                       (size_t)(py0 + sy) * 384 + px0) = v;
        }
    }
}

// ============================================================================
// Launch
// ============================================================================
extern "C" void kernel_launch(void* const* d_in, const int* in_sizes, int n_in,
                              void* d_out, int out_size) {
    const float* x     = (const float*)d_in[0];  // (8,32,192,192)
    const float* alpha = (const float*)d_in[1];  // (2,8,1,384,384)
    const float* wts   = (const float*)d_in[2];  // (16,32,9)
    const float* bias  = (const float*)d_in[3];  // (16,)
    float* out = (float*)d_out;                  // (8,16,384,384)

    (void)in_sizes; (void)n_in; (void)out_size;

    const int smem2 = 144 * 18 * 19 * 4;  // 196992 bytes
    cudaFuncSetAttribute(pass2, cudaFuncAttributeMaxDynamicSharedMemorySize, smem2);

    pass1<<<dim3(192, 8), 384>>>(x, wts);
    pass2<<<dim3(12, 12, 8), 512, smem2>>>(alpha, bias, out);
}

// round 4
// speedup vs baseline: 1.1962x; 1.1962x over previous
#include <cuda_runtime.h>
#include <cstdint>
#include <cstddef>

// ============================================================================
// Compile-time basis construction (double precision, folded to fp32 literals)
// ============================================================================
__host__ __device__ constexpr double cexp_(double v) {
    double t = 1.0, s = 1.0;
    for (int n = 1; n < 90; ++n) { t *= v / n; s += t; }
    return s;
}
__host__ __device__ constexpr double csqrt_(double v) {
    if (v <= 0.0) return 0.0;
    double x = v < 1.0 ? 1.0 : v;
    for (int i = 0; i < 80; ++i) x = 0.5 * (x + v / x);
    return x;
}

struct Basis {
    float b0[3][5][5];      // ring bases (k=0), r0 = 0,1,2
    float br[3][2][5][5];   // ring(r0)*cos(k*theta), k=1..3, r0 = 1,2
    float bi[3][2][5][5];   // ring(r0)*sin(k*theta)
};

__host__ __device__ constexpr Basis make_basis() {
    Basis B{};
    for (int yy = 0; yy < 5; ++yy) {
        for (int xx = 0; xx < 5; ++xx) {
            double ys = yy - 2.0, xs = xx - 2.0;
            double r = csqrt_(ys * ys + xs * xs);
            double cth = r > 0.0 ? xs / r : 1.0;
            double sth = r > 0.0 ? ys / r : 0.0;
            double ring0 = cexp_(-(r - 0.0) * (r - 0.0) / 0.72);
            double ring1 = cexp_(-(r - 1.0) * (r - 1.0) / 0.72);
            double ring2 = cexp_(-(r - 2.0) * (r - 2.0) / 0.72);
            B.b0[0][yy][xx] = (float)ring0;
            B.b0[1][yy][xx] = (float)ring1;
            B.b0[2][yy][xx] = (float)ring2;
            double ck = cth, sk = sth;
            for (int k = 0; k < 3; ++k) {
                B.br[k][0][yy][xx] = (float)(ring1 * ck);
                B.br[k][1][yy][xx] = (float)(ring2 * ck);
                B.bi[k][0][yy][xx] = (float)(ring1 * sk);
                B.bi[k][1][yy][xx] = (float)(ring2 * sk);
                double cn = ck * cth - sk * sth;
                double sn = sk * cth + ck * sth;
                ck = cn; sk = sn;
            }
        }
    }
    return B;
}

// ============================================================================
// Intermediate: y[n][o*9+c][192*192]
// ============================================================================
__device__ float g_y[(size_t)8 * 144 * 192 * 192];

// ============================================================================
// Pass 1: y[n, o*9+c, p] = sum_i weights[o,i,c] * x[n,i,p]
// Inner loop uses packed fma.rn.f32x2 (2 fp32 lanes/issue; ptxas won't emit
// this from plain C++ fmaf).
// ============================================================================
#define FMA2(acc, a, b) \
    asm("fma.rn.f32x2 %0, %1, %2, %0;" : "+l"(acc) : "l"(a), "l"(b))
#define SPLAT2(dst, f) \
    asm("mov.b64 %0, {%1, %1};" : "=l"(dst) : "f"(f))

__global__ __launch_bounds__(384) void pass1(const float* __restrict__ x,
                                             const float* __restrict__ wts) {
    __shared__ float xs[32 * 192];      // [i][p]
    __shared__ float ws[144 * 33];      // [(o,c)][i], padded
    const int n = blockIdx.y;
    const int p0 = blockIdx.x * 192;
    const int tid = threadIdx.x;

    for (int e = tid; e < 4608; e += 384) {
        int o = e / 288, r = e % 288, i = r / 9, c = r % 9;
        ws[(o * 9 + c) * 33 + i] = wts[e];
    }
    const float* xb = x + (size_t)n * 32 * 36864 + p0;
    for (int e = tid; e < 1536; e += 384) {
        int i = e / 48, p4 = e % 48;
        *(float4*)(xs + i * 192 + p4 * 4) =
            *(const float4*)(xb + (size_t)i * 36864 + p4 * 4);
    }
    __syncthreads();

    const int o  = tid & 15;
    const int pg = tid >> 4;   // 0..23, 8 pixels each

    unsigned long long acc2[9][4];
#pragma unroll
    for (int c = 0; c < 9; ++c)
#pragma unroll
        for (int j = 0; j < 4; ++j) acc2[c][j] = 0ULL;

    const float* xg = xs + pg * 8;
    const float* wg = ws + o * 9 * 33;

#pragma unroll 4
    for (int i = 0; i < 32; ++i) {
        longlong2 t0 = *(const longlong2*)(xg + i * 192);       // px 0-3
        longlong2 t1 = *(const longlong2*)(xg + i * 192 + 4);   // px 4-7
        unsigned long long xa[4] = {(unsigned long long)t0.x, (unsigned long long)t0.y,
                                    (unsigned long long)t1.x, (unsigned long long)t1.y};
#pragma unroll
        for (int c = 0; c < 9; ++c) {
            unsigned long long w2;
            SPLAT2(w2, wg[c * 33 + i]);
#pragma unroll
            for (int j = 0; j < 4; ++j) FMA2(acc2[c][j], w2, xa[j]);
        }
    }

    size_t base = ((size_t)n * 144 + o * 9) * 36864 + p0 + pg * 8;
#pragma unroll
    for (int c = 0; c < 9; ++c) {
        float* yo = g_y + base + (size_t)c * 36864;
        longlong2 s0, s1;
        s0.x = (long long)acc2[c][0]; s0.y = (long long)acc2[c][1];
        s1.x = (long long)acc2[c][2]; s1.y = (long long)acc2[c][3];
        *(longlong2*)yo       = s0;
        *(longlong2*)(yo + 4) = s1;
    }
}

// ============================================================================
// Pass 2: steered transpose-conv combine + modulation + rho/bias epilogue.
// o-range split across blocks (grid.z = n*2 + oh): stage 72 channels -> 96 KB
// smem -> 2 CTA/SM (32 warps) instead of 1.
// Thread = (quad, o-subhalf): 256 quads x 2, each thread does 4 o.
// ============================================================================
__device__ __forceinline__ float dotT(const float (&T)[5][5],
                                      const float (&w)[3][3],
                                      int SY, int SX) {
    float s = 0.f;
#pragma unroll
    for (int dy = 0; dy < 3; ++dy) {
        if (dy < SY) continue;
        int vy = (SY ? 5 : 4) - 2 * dy;
#pragma unroll
        for (int dx = 0; dx < 3; ++dx) {
            if (dx < SX) continue;
            int vx = (SX ? 5 : 4) - 2 * dx;
            float cf = T[vy][vx];
            if (cf != 0.f) s += cf * w[dy][dx];
        }
    }
    return s;
}

__global__ __launch_bounds__(512, 2) void pass2(const float* __restrict__ alpha,
                                                const float* __restrict__ bias,
                                                float* __restrict__ out) {
    constexpr Basis BAS = make_basis();
    extern __shared__ float ysm[];   // [72][18][19]

    const int tx = blockIdx.x, ty = blockIdx.y;
    const int n  = blockIdx.z >> 1;
    const int oh = blockIdx.z & 1;       // o half: 0 -> o 0..7, 1 -> o 8..15
    const int tid = threadIdx.x;
    const int ix0 = tx * 16, iy0 = ty * 16;

    // Stage 72 channels (o in [oh*8, oh*8+8)) with 1-halo
    const float* yg = g_y + ((size_t)n * 144 + oh * 72) * 36864;
    for (int e = tid; e < 72 * 324; e += 512) {
        int oc = e / 324;
        int rem = e - oc * 324;
        int r = rem / 18;
        int cc = rem - r * 18;
        int gy = iy0 - 1 + r, gx = ix0 - 1 + cc;
        float v = 0.f;
        if ((unsigned)gy < 192u && (unsigned)gx < 192u)
            v = yg[(size_t)oc * 36864 + gy * 192 + gx];
        ysm[(oc * 18 + r) * 19 + cc] = v;
    }
    __syncthreads();

    const int q  = tid & 255;  // quad id (16x16 quads = 32x32 px tile)
    const int os = tid >> 8;   // o sub-half: 4 o each
    const int qy = q >> 4, qx = q & 15;
    const int py0 = ty * 32 + 2 * qy;
    const int px0 = tx * 32 + 2 * qx;

    // Per-pixel modulation (Chebyshev recursion)
    float RHO[2][2], CK[3][2][2], SK[3][2][2];
    {
        const float* a0p = alpha + (size_t)n * 147456 + (size_t)py0 * 384 + px0;
        const float* a1p = a0p + (size_t)8 * 147456;
#pragma unroll
        for (int sy = 0; sy < 2; ++sy)
#pragma unroll
            for (int sx = 0; sx < 2; ++sx) {
                float a0 = a0p[sy * 384 + sx];
                float a1 = a1p[sy * 384 + sx];
                float rho = sqrtf(a0 * a0 + a1 * a1);
                float inv = 1.0f / (rho + 1e-8f);
                float c1 = a0 * inv, s1 = a1 * inv;
                float c2 = c1 * c1 - s1 * s1;
                float s2 = s1 * c1 + c1 * s1;
                float c3 = c2 * c1 - s2 * s1;
                float s3 = s2 * c1 + c2 * s1;
                RHO[sy][sx] = rho;
                CK[0][sy][sx] = c1; SK[0][sy][sx] = s1;
                CK[1][sy][sx] = c2; SK[1][sy][sx] = s2;
                CK[2][sy][sx] = c3; SK[2][sy][sx] = s3;
            }
    }

    for (int ol = os * 4; ol < os * 4 + 4; ++ol) {
        const int o = oh * 8 + ol;
        float acc[2][2] = {{0.f, 0.f}, {0.f, 0.f}};
#pragma unroll
        for (int c = 0; c < 9; ++c) {
            const float* wbp = ysm + ((ol * 9 + c) * 18 + qy) * 19 + qx;
            float w[3][3];
#pragma unroll
            for (int dy = 0; dy < 3; ++dy)
#pragma unroll
                for (int dx = 0; dx < 3; ++dx) w[dy][dx] = wbp[dy * 19 + dx];

            if (c < 3) {
                acc[0][0] += dotT(BAS.b0[c], w, 0, 0);
                acc[0][1] += dotT(BAS.b0[c], w, 0, 1);
                acc[1][0] += dotT(BAS.b0[c], w, 1, 0);
                acc[1][1] += dotT(BAS.b0[c], w, 1, 1);
            } else {
                const int k = (c - 3) >> 1;
                const int j = (c - 3) & 1;
#pragma unroll
                for (int sy = 0; sy < 2; ++sy)
#pragma unroll
                    for (int sx = 0; sx < 2; ++sx) {
                        float dR = dotT(BAS.br[k][j], w, sy, sx);
                        float dI = dotT(BAS.bi[k][j], w, sy, sx);
                        acc[sy][sx] += dR * CK[k][sy][sx] + dI * SK[k][sy][sx];
                    }
            }
        }
        float bo = bias[o];
#pragma unroll
        for (int sy = 0; sy < 2; ++sy) {
            float2 v;
            v.x = RHO[sy][0] * acc[sy][0] + bo;
            v.y = RHO[sy][1] * acc[sy][1] + bo;
            *(float2*)(out + ((size_t)(n * 16 + o)) * 147456 +
                       (size_t)(py0 + sy) * 384 + px0) = v;
        }
    }
}

// ============================================================================
// Launch
// ============================================================================
extern "C" void kernel_launch(void* const* d_in, const int* in_sizes, int n_in,
                              void* d_out, int out_size) {
    const float* x     = (const float*)d_in[0];  // (8,32,192,192)
    const float* alpha = (const float*)d_in[1];  // (2,8,1,384,384)
    const float* wts   = (const float*)d_in[2];  // (16,32,9)
    const float* bias  = (const float*)d_in[3];  // (16,)
    float* out = (float*)d_out;                  // (8,16,384,384)

    (void)in_sizes; (void)n_in; (void)out_size;

    const int smem2 = 72 * 18 * 19 * 4;  // 98496 bytes
    cudaFuncSetAttribute(pass2, cudaFuncAttributeMaxDynamicSharedMemorySize, smem2);

    pass1<<<dim3(192, 8), 384>>>(x, wts);
    pass2<<<dim3(12, 12, 16), 512, smem2>>>(alpha, bias, out);
}

// round 5
// speedup vs baseline: 1.3321x; 1.1136x over previous
#include <cuda_runtime.h>
#include <cstdint>
#include <cstddef>

// ============================================================================
// Compile-time basis construction
// ============================================================================
__host__ __device__ constexpr double cexp_(double v) {
    double t = 1.0, s = 1.0;
    for (int n = 1; n < 90; ++n) { t *= v / n; s += t; }
    return s;
}
__host__ __device__ constexpr double csqrt_(double v) {
    if (v <= 0.0) return 0.0;
    double x = v < 1.0 ? 1.0 : v;
    for (int i = 0; i < 80; ++i) x = 0.5 * (x + v / x);
    return x;
}

struct Basis {
    float b0[3][5][5];
    float br[3][2][5][5];
    float bi[3][2][5][5];
};

__host__ __device__ constexpr Basis make_basis() {
    Basis B{};
    for (int yy = 0; yy < 5; ++yy) {
        for (int xx = 0; xx < 5; ++xx) {
            double ys = yy - 2.0, xs = xx - 2.0;
            double r = csqrt_(ys * ys + xs * xs);
            double cth = r > 0.0 ? xs / r : 1.0;
            double sth = r > 0.0 ? ys / r : 0.0;
            double ring0 = cexp_(-(r - 0.0) * (r - 0.0) / 0.72);
            double ring1 = cexp_(-(r - 1.0) * (r - 1.0) / 0.72);
            double ring2 = cexp_(-(r - 2.0) * (r - 2.0) / 0.72);
            B.b0[0][yy][xx] = (float)ring0;
            B.b0[1][yy][xx] = (float)ring1;
            B.b0[2][yy][xx] = (float)ring2;
            double ck = cth, sk = sth;
            for (int k = 0; k < 3; ++k) {
                B.br[k][0][yy][xx] = (float)(ring1 * ck);
                B.br[k][1][yy][xx] = (float)(ring2 * ck);
                B.bi[k][0][yy][xx] = (float)(ring1 * sk);
                B.bi[k][1][yy][xx] = (float)(ring2 * sk);
                double cn = ck * cth - sk * sth;
                double sn = sk * cth + ck * sth;
                ck = cn; sk = sn;
            }
        }
    }
    return B;
}

// ============================================================================
// Globals
// ============================================================================
__device__ float g_y[(size_t)8 * 144 * 192 * 192];
__device__ float g_wt[4608];   // [(o*9+c)*32 + i]

// ============================================================================
// Pass 0: transpose weights (o,i,c) -> [(o,c)][i]
// ============================================================================
__global__ void wtrans(const float* __restrict__ wts) {
    int e = blockIdx.x * 512 + threadIdx.x;   // 9 blocks x 512 = 4608
    int o = e / 288, r = e % 288, i = r / 9, c = r % 9;
    g_wt[(o * 9 + c) * 32 + i] = wts[e];
}

// ============================================================================
// Pass 1: y[n, o*9+c, p] = sum_i w[o,i,c] * x[n,i,p]
// 256 thr = 16 o x 16 px-groups (4 px each), 4 CTA/SM. f32x2 packed FMA.
// ============================================================================
#define FMA2(acc, a, b) \
    asm("fma.rn.f32x2 %0, %1, %2, %0;" : "+l"(acc) : "l"(a), "l"(b))
#define SPLAT2(dst, f) \
    asm("mov.b64 %0, {%1, %1};" : "=l"(dst) : "f"(f))

__global__ __launch_bounds__(256, 4) void pass1(const float* __restrict__ x) {
    __shared__ float xs[32 * 64];       // [i][p], 8 KB
    __shared__ float ws[144 * 33];      // [(o,c)][i] pad 33, 19 KB
    const int n = blockIdx.y;
    const int p0 = blockIdx.x * 64;
    const int tid = threadIdx.x;

    for (int e = tid; e < 4608; e += 256)
        ws[(e >> 5) * 33 + (e & 31)] = g_wt[e];

    const float* xb = x + (size_t)n * 32 * 36864 + p0;
    for (int e = tid; e < 512; e += 256) {
        int i = e >> 4, p4 = e & 15;
        *(float4*)(xs + i * 64 + p4 * 4) =
            *(const float4*)(xb + (size_t)i * 36864 + p4 * 4);
    }
    __syncthreads();

    const int o  = tid & 15;
    const int pg = tid >> 4;   // 0..15, 4 px each

    unsigned long long acc2[9][2];
#pragma unroll
    for (int c = 0; c < 9; ++c) { acc2[c][0] = 0ULL; acc2[c][1] = 0ULL; }

    const float* xg = xs + pg * 4;
    const float* wg = ws + o * 297;

#pragma unroll 8
    for (int i = 0; i < 32; ++i) {
        longlong2 t0 = *(const longlong2*)(xg + i * 64);
        unsigned long long x0 = (unsigned long long)t0.x;
        unsigned long long x1 = (unsigned long long)t0.y;
#pragma unroll
        for (int c = 0; c < 9; ++c) {
            unsigned long long w2;
            SPLAT2(w2, wg[c * 33 + i]);
            FMA2(acc2[c][0], w2, x0);
            FMA2(acc2[c][1], w2, x1);
        }
    }

    size_t base = ((size_t)n * 144 + o * 9) * 36864 + p0 + pg * 4;
#pragma unroll
    for (int c = 0; c < 9; ++c) {
        longlong2 s;
        s.x = (long long)acc2[c][0];
        s.y = (long long)acc2[c][1];
        *(longlong2*)(g_y + base + (size_t)c * 36864) = s;
    }
}

// ============================================================================
// Pass 2: steered transpose-conv combine + modulation + epilogue.
// grid.z = n*2 + oh (72-channel smem split, 2 CTA/SM).
// Rolling Chebyshev modulation (no CK/SK arrays -> fewer regs).
// ============================================================================
__device__ __forceinline__ float dotT(const float (&T)[5][5],
                                      const float (&w)[3][3],
                                      int SY, int SX) {
    float s = 0.f;
#pragma unroll
    for (int dy = 0; dy < 3; ++dy) {
        if (dy < SY) continue;
        int vy = (SY ? 5 : 4) - 2 * dy;
#pragma unroll
        for (int dx = 0; dx < 3; ++dx) {
            if (dx < SX) continue;
            int vx = (SX ? 5 : 4) - 2 * dx;
            float cf = T[vy][vx];
            if (cf != 0.f) s += cf * w[dy][dx];
        }
    }
    return s;
}

__global__ __launch_bounds__(512, 2) void pass2(const float* __restrict__ alpha,
                                                const float* __restrict__ bias,
                                                float* __restrict__ out) {
    constexpr Basis BAS = make_basis();
    extern __shared__ float ysm[];   // [72][18][19]

    const int tx = blockIdx.x, ty = blockIdx.y;
    const int n  = blockIdx.z >> 1;
    const int oh = blockIdx.z & 1;
    const int tid = threadIdx.x;
    const int ix0 = tx * 16, iy0 = ty * 16;

    const float* yg = g_y + ((size_t)n * 144 + oh * 72) * 36864;
    const bool interior = (tx > 0) & (tx < 11) & (ty > 0) & (ty < 11);
    if (interior) {
        for (int e = tid; e < 72 * 324; e += 512) {
            int oc = e / 324;
            int rem = e - oc * 324;
            int r = rem / 18;
            int cc = rem - r * 18;
            ysm[(oc * 18 + r) * 19 + cc] =
                yg[(size_t)oc * 36864 + (iy0 - 1 + r) * 192 + (ix0 - 1 + cc)];
        }
    } else {
        for (int e = tid; e < 72 * 324; e += 512) {
            int oc = e / 324;
            int rem = e - oc * 324;
            int r = rem / 18;
            int cc = rem - r * 18;
            int gy = iy0 - 1 + r, gx = ix0 - 1 + cc;
            float v = 0.f;
            if ((unsigned)gy < 192u && (unsigned)gx < 192u)
                v = yg[(size_t)oc * 36864 + gy * 192 + gx];
            ysm[(oc * 18 + r) * 19 + cc] = v;
        }
    }
    __syncthreads();

    const int q  = tid & 255;
    const int os = tid >> 8;       // 4 o each
    const int qy = q >> 4, qx = q & 15;
    const int py0 = ty * 32 + 2 * qy;
    const int px0 = tx * 32 + 2 * qx;

    // First-harmonic direction + magnitude per pixel
    float C1[2][2], S1[2][2], RHO[2][2];
    {
        const float* a0p = alpha + (size_t)n * 147456 + (size_t)py0 * 384 + px0;
        const float* a1p = a0p + (size_t)8 * 147456;
#pragma unroll
        for (int sy = 0; sy < 2; ++sy)
#pragma unroll
            for (int sx = 0; sx < 2; ++sx) {
                float a0 = a0p[sy * 384 + sx];
                float a1 = a1p[sy * 384 + sx];
                float rho = sqrtf(a0 * a0 + a1 * a1);
                float inv = 1.0f / (rho + 1e-8f);
                RHO[sy][sx] = rho;
                C1[sy][sx] = a0 * inv;
                S1[sy][sx] = a1 * inv;
            }
    }

    for (int ol = os * 4; ol < os * 4 + 4; ++ol) {
        const int o = oh * 8 + ol;
        float acc[2][2] = {{0.f, 0.f}, {0.f, 0.f}};
        float ck[2][2], sk[2][2];
#pragma unroll
        for (int sy = 0; sy < 2; ++sy)
#pragma unroll
            for (int sx = 0; sx < 2; ++sx) { ck[sy][sx] = C1[sy][sx]; sk[sy][sx] = S1[sy][sx]; }

#pragma unroll
        for (int c = 0; c < 9; ++c) {
            // advance harmonic rotation when k increments (c = 5, 7)
            if (c == 5 || c == 7) {
#pragma unroll
                for (int sy = 0; sy < 2; ++sy)
#pragma unroll
                    for (int sx = 0; sx < 2; ++sx) {
                        float cn = ck[sy][sx] * C1[sy][sx] - sk[sy][sx] * S1[sy][sx];
                        float sn = sk[sy][sx] * C1[sy][sx] + ck[sy][sx] * S1[sy][sx];
                        ck[sy][sx] = cn; sk[sy][sx] = sn;
                    }
            }
            const float* wbp = ysm + ((ol * 9 + c) * 18 + qy) * 19 + qx;
            float w[3][3];
#pragma unroll
            for (int dy = 0; dy < 3; ++dy)
#pragma unroll
                for (int dx = 0; dx < 3; ++dx) w[dy][dx] = wbp[dy * 19 + dx];

            if (c < 3) {
                acc[0][0] += dotT(BAS.b0[c], w, 0, 0);
                acc[0][1] += dotT(BAS.b0[c], w, 0, 1);
                acc[1][0] += dotT(BAS.b0[c], w, 1, 0);
                acc[1][1] += dotT(BAS.b0[c], w, 1, 1);
            } else {
                const int k = (c - 3) >> 1;
                const int j = (c - 3) & 1;
#pragma unroll
                for (int sy = 0; sy < 2; ++sy)
#pragma unroll
                    for (int sx = 0; sx < 2; ++sx) {
                        float dR = dotT(BAS.br[k][j], w, sy, sx);
                        float dI = dotT(BAS.bi[k][j], w, sy, sx);
                        acc[sy][sx] += dR * ck[sy][sx] + dI * sk[sy][sx];
                    }
            }
        }
        float bo = bias[o];
#pragma unroll
        for (int sy = 0; sy < 2; ++sy) {
            float2 v;
            v.x = RHO[sy][0] * acc[sy][0] + bo;
            v.y = RHO[sy][1] * acc[sy][1] + bo;
            *(float2*)(out + ((size_t)(n * 16 + o)) * 147456 +
                       (size_t)(py0 + sy) * 384 + px0) = v;
        }
    }
}

// ============================================================================
// Launch
// ============================================================================
extern "C" void kernel_launch(void* const* d_in, const int* in_sizes, int n_in,
                              void* d_out, int out_size) {
    const float* x     = (const float*)d_in[0];  // (8,32,192,192)
    const float* alpha = (const float*)d_in[1];  // (2,8,1,384,384)
    const float* wts   = (const float*)d_in[2];  // (16,32,9)
    const float* bias  = (const float*)d_in[3];  // (16,)
    float* out = (float*)d_out;                  // (8,16,384,384)

    (void)in_sizes; (void)n_in; (void)out_size;

    const int smem2 = 72 * 18 * 19 * 4;  // 98496 bytes
    cudaFuncSetAttribute(pass2, cudaFuncAttributeMaxDynamicSharedMemorySize, smem2);

    wtrans<<<9, 512>>>(wts);
    pass1<<<dim3(576, 8), 256>>>(x);
    pass2<<<dim3(12, 12, 16), 512, smem2>>>(alpha, bias, out);
}